// round 4
// baseline (speedup 1.0000x reference)
#include <cuda_runtime.h>
#include <math.h>

// Problem shape (fixed by setup_inputs)
#define FM_B 2
#define FM_C 256
#define FM_H 50
#define FM_W 50
#define POOL_H 7
#define POOL_W 7

__global__ void roi_max_pool_kernel(const float* __restrict__ fm,
                                    const float* __restrict__ rois,
                                    float* __restrict__ out,
                                    int total) {
    int idx = blockIdx.x * blockDim.x + threadIdx.x;
    if (idx >= total) return;

    int bin = idx % (POOL_H * POOL_W);
    int rc  = idx / (POOL_H * POOL_W);
    int c   = rc % FM_C;
    int r   = rc / FM_C;
    int pw  = bin % POOL_W;
    int ph  = bin / POOL_W;

    const float* roi = rois + r * 5;
    int b  = (int)roi[0];
    // jnp.round = round-half-to-even = rintf (RN mode)
    int x1 = (int)rintf(roi[1]);
    int y1 = (int)rintf(roi[2]);
    int x2 = (int)rintf(roi[3]);
    int y2 = (int)rintf(roi[4]);

    int roi_w = max(x2 - x1 + 1, 1);
    int roi_h = max(y2 - y1 + 1, 1);

    // Replicate XLA fast-math semantics: x / 7  ->  x * fl(1/7).
    // fl(1/7) = 0x3E124925 is strictly ABOVE 1/7, which perturbs ceil edges
    // upward exactly where the reference's windows are wider than exact math.
    const float RCP7 = __uint_as_float(0x3E124925u);
    float bin_w = __fmul_rn((float)roi_w, RCP7);
    float bin_h = __fmul_rn((float)roi_h, RCP7);

    int ws = x1 + (int)floorf(__fmul_rn((float)pw,       bin_w));
    int we = x1 + (int)ceilf (__fmul_rn((float)(pw + 1), bin_w));
    int hs = y1 + (int)floorf(__fmul_rn((float)ph,       bin_h));
    int he = y1 + (int)ceilf (__fmul_rn((float)(ph + 1), bin_h));

    ws = min(max(ws, 0), FM_W);
    we = min(max(we, 0), FM_W);
    hs = min(max(hs, 0), FM_H);
    he = min(max(he, 0), FM_H);

    const float* base = fm + ((size_t)b * FM_C + c) * (FM_H * FM_W);

    float m = -INFINITY;
    for (int h = hs; h < he; ++h) {
        const float* row = base + h * FM_W;
        #pragma unroll 4
        for (int w = ws; w < we; ++w) {
            m = fmaxf(m, __ldg(row + w));
        }
    }
    // Empty bin -> 0 (reference's isinf -> 0 rule)
    out[idx] = isinf(m) ? 0.0f : m;
}

extern "C" void kernel_launch(void* const* d_in, const int* in_sizes, int n_in,
                              void* d_out, int out_size) {
    const float* fm   = (const float*)d_in[0];
    const float* rois = (const float*)d_in[1];
    float* out        = (float*)d_out;

    int total = out_size;  // R * C * PH * PW
    int threads = 256;
    int blocks = (total + threads - 1) / threads;
    roi_max_pool_kernel<<<blocks, threads>>>(fm, rois, out, total);
}